// round 1
// baseline (speedup 1.0000x reference)
#include <cuda_runtime.h>
#include <cuda_bf16.h>
#include <cstdint>

// QKVAttentionLegacy: qkv fp32 (4, 3072, 2048) -> out fp32 (4, 1024, 2048)
// 64 heads (b = bb*16 + h), C=64, T=S=2048, channel-major q/k/v [b][c][t].
// Flash-attention, fp32, packed f32x2 FMA, 1 CTA = (head, 64-query tile).

#define NTHREADS 256
#define TILE_T 64
#define TILE_S 64
#define SEQ 2048
#define LOG2E 1.4426950408889634f

// Smem layout (floats): Qs 64*64 | Ks 64*64 | Vts 64*68 | Ps 64*68 | mrow 64 | lrow 64 | arow 64
#define SMEM_FLOATS (4096 + 4096 + 64*68 + 64*68 + 192)
#define SMEM_BYTES (SMEM_FLOATS * 4)

__device__ __forceinline__ unsigned long long pk2(float x, float y) {
    unsigned long long r;
    asm("mov.b64 %0, {%1, %2};" : "=l"(r) : "f"(x), "f"(y));
    return r;
}
__device__ __forceinline__ float2 up2(unsigned long long v) {
    float2 f;
    asm("mov.b64 {%0, %1}, %2;" : "=f"(f.x), "=f"(f.y) : "l"(v));
    return f;
}
__device__ __forceinline__ void fma2(unsigned long long &d, unsigned long long a, unsigned long long b) {
    asm("fma.rn.f32x2 %0, %1, %2, %0;" : "+l"(d) : "l"(a), "l"(b));
}
__device__ __forceinline__ void mul2(unsigned long long &d, unsigned long long a) {
    asm("mul.rn.f32x2 %0, %0, %1;" : "+l"(d) : "l"(a));
}
__device__ __forceinline__ float ex2f_(float x) {
    float r;
    asm("ex2.approx.ftz.f32 %0, %1;" : "=f"(r) : "f"(x));
    return r;
}

__global__ __launch_bounds__(NTHREADS)
void qkv_attn_kernel(const float* __restrict__ qkv, float* __restrict__ out)
{
    extern __shared__ float sm[];
    float* Qs   = sm;                    // [c][t]  stride 64
    float* Ks   = sm + 4096;             // [c][s]  stride 64
    float* Vts  = sm + 8192;             // [s][c]  stride 68
    float* Ps   = Vts + 64 * 68;         // [s][t]  stride 68
    float* mrow = Ps + 64 * 68;          // [t] running max
    float* lrow = mrow + 64;             // [t] running sum
    float* arow = lrow + 64;             // [t] rescale factor this iter

    const int tid = threadIdx.x;
    const int ty  = tid >> 4;            // 0..15 -> t rows 4ty..4ty+3 (gemm1) / c rows (gemm2)
    const int tx  = tid & 15;            // 0..15 -> s cols 4tx..4tx+3 (gemm1) / t cols (gemm2)
    const int b   = blockIdx.y;          // head 0..63
    const int t0  = blockIdx.x * TILE_T;
    const int bb  = b >> 4;
    const int h   = b & 15;

    const float* qg = qkv + ((size_t)bb * 3072 + (size_t)h * 192) * SEQ;
    const float* kg = qg + (size_t)64 * SEQ;
    const float* vg = qg + (size_t)128 * SEQ;
    float*       og = out + (size_t)b * 64 * SEQ;

    // ---- prologue: load Q tile (scale^2 = 1/8 folded in), init stats ----
    #pragma unroll
    for (int idx = tid; idx < 1024; idx += NTHREADS) {
        int r = idx >> 4, c4 = (idx & 15) << 2;
        float4 q4 = *(const float4*)&qg[(size_t)r * SEQ + t0 + c4];
        q4.x *= 0.125f; q4.y *= 0.125f; q4.z *= 0.125f; q4.w *= 0.125f;
        *(float4*)&Qs[r * 64 + c4] = q4;
    }
    if (tid < 64) { mrow[tid] = -INFINITY; lrow[tid] = 0.0f; }

    unsigned long long Oa[4][2];
    #pragma unroll
    for (int i = 0; i < 4; i++) { Oa[i][0] = 0ull; Oa[i][1] = 0ull; }

    for (int st = 0; st < SEQ / TILE_S; ++st) {
        const int s0 = st * TILE_S;

        __syncthreads();   // previous gemm2 done with Vts/Ps; prologue visible on iter 0

        // ---- load K tile [c][s], V tile transposed [s][c] ----
        #pragma unroll
        for (int idx = tid; idx < 1024; idx += NTHREADS) {
            int r = idx >> 4, c4 = (idx & 15) << 2;
            *(float4*)&Ks[r * 64 + c4] = *(const float4*)&kg[(size_t)r * SEQ + s0 + c4];
            float4 v4 = *(const float4*)&vg[(size_t)r * SEQ + s0 + c4];
            Vts[(c4 + 0) * 68 + r] = v4.x;
            Vts[(c4 + 1) * 68 + r] = v4.y;
            Vts[(c4 + 2) * 68 + r] = v4.z;
            Vts[(c4 + 3) * 68 + r] = v4.w;
        }
        __syncthreads();

        // ---- gemm1: S[t][s] = sum_c Q[c][t] * K[c][s]  (scale folded in Q) ----
        unsigned long long Sa[4][2];
        #pragma unroll
        for (int i = 0; i < 4; i++) { Sa[i][0] = 0ull; Sa[i][1] = 0ull; }

        #pragma unroll 8
        for (int c = 0; c < 64; c++) {
            float4 a4 = *(const float4*)&Qs[c * 64 + (ty << 2)];
            float4 b4 = *(const float4*)&Ks[c * 64 + (tx << 2)];
            unsigned long long b01 = pk2(b4.x, b4.y), b23 = pk2(b4.z, b4.w);
            unsigned long long aa;
            aa = pk2(a4.x, a4.x); fma2(Sa[0][0], aa, b01); fma2(Sa[0][1], aa, b23);
            aa = pk2(a4.y, a4.y); fma2(Sa[1][0], aa, b01); fma2(Sa[1][1], aa, b23);
            aa = pk2(a4.z, a4.z); fma2(Sa[2][0], aa, b01); fma2(Sa[2][1], aa, b23);
            aa = pk2(a4.w, a4.w); fma2(Sa[3][0], aa, b01); fma2(Sa[3][1], aa, b23);
        }

        // ---- online softmax (row = t, 16 lanes per row = half warp) ----
        #pragma unroll
        for (int i = 0; i < 4; i++) {
            float2 u0 = up2(Sa[i][0]), u1 = up2(Sa[i][1]);
            float sv0 = u0.x, sv1 = u0.y, sv2 = u1.x, sv3 = u1.y;
            int t = (ty << 2) + i;

            float mloc = fmaxf(fmaxf(sv0, sv1), fmaxf(sv2, sv3));
            #pragma unroll
            for (int m = 8; m; m >>= 1)
                mloc = fmaxf(mloc, __shfl_xor_sync(0xffffffffu, mloc, m));

            float mprev = mrow[t];
            float mnew  = fmaxf(mprev, mloc);

            float p0 = ex2f_((sv0 - mnew) * LOG2E);
            float p1 = ex2f_((sv1 - mnew) * LOG2E);
            float p2 = ex2f_((sv2 - mnew) * LOG2E);
            float p3 = ex2f_((sv3 - mnew) * LOG2E);
            float ps = p0 + p1 + p2 + p3;
            #pragma unroll
            for (int m = 8; m; m >>= 1)
                ps += __shfl_xor_sync(0xffffffffu, ps, m);

            if (tx == 0) {
                float al = ex2f_((mprev - mnew) * LOG2E);
                mrow[t] = mnew;
                lrow[t] = lrow[t] * al + ps;
                arow[t] = al;
            }
            Ps[((tx << 2) + 0) * 68 + t] = p0;
            Ps[((tx << 2) + 1) * 68 + t] = p1;
            Ps[((tx << 2) + 2) * 68 + t] = p2;
            Ps[((tx << 2) + 3) * 68 + t] = p3;
        }
        __syncthreads();

        // ---- rescale running O by alpha[t] ----
        {
            float4 av = *(const float4*)&arow[tx << 2];
            unsigned long long al01 = pk2(av.x, av.y), al23 = pk2(av.z, av.w);
            #pragma unroll
            for (int i = 0; i < 4; i++) { mul2(Oa[i][0], al01); mul2(Oa[i][1], al23); }
        }

        // ---- gemm2: O[c][t] += sum_s V[c][s] * P[t][s] ----
        #pragma unroll 8
        for (int s = 0; s < 64; s++) {
            float4 v4 = *(const float4*)&Vts[s * 68 + (ty << 2)];
            float4 p4 = *(const float4*)&Ps[s * 68 + (tx << 2)];
            unsigned long long p01 = pk2(p4.x, p4.y), p23 = pk2(p4.z, p4.w);
            unsigned long long vv;
            vv = pk2(v4.x, v4.x); fma2(Oa[0][0], vv, p01); fma2(Oa[0][1], vv, p23);
            vv = pk2(v4.y, v4.y); fma2(Oa[1][0], vv, p01); fma2(Oa[1][1], vv, p23);
            vv = pk2(v4.z, v4.z); fma2(Oa[2][0], vv, p01); fma2(Oa[2][1], vv, p23);
            vv = pk2(v4.w, v4.w); fma2(Oa[3][0], vv, p01); fma2(Oa[3][1], vv, p23);
        }
    }

    // ---- epilogue: normalize by row sum, write out[b][c][t] (coalesced float4) ----
    float4 lv = *(const float4*)&lrow[tx << 2];
    float li0 = 1.0f / lv.x, li1 = 1.0f / lv.y, li2 = 1.0f / lv.z, li3 = 1.0f / lv.w;
    #pragma unroll
    for (int i = 0; i < 4; i++) {
        float2 o0 = up2(Oa[i][0]), o1 = up2(Oa[i][1]);
        float4 o = make_float4(o0.x * li0, o0.y * li1, o1.x * li2, o1.y * li3);
        *(float4*)&og[(size_t)((ty << 2) + i) * SEQ + t0 + (tx << 2)] = o;
    }
}

extern "C" void kernel_launch(void* const* d_in, const int* in_sizes, int n_in,
                              void* d_out, int out_size)
{
    const float* qkv = (const float*)d_in[0];
    float* out = (float*)d_out;

    cudaFuncSetAttribute(qkv_attn_kernel,
                         cudaFuncAttributeMaxDynamicSharedMemorySize, SMEM_BYTES);

    dim3 grid(SEQ / TILE_T, 64);   // (32, 64) = 2048 CTAs
    qkv_attn_kernel<<<grid, NTHREADS, SMEM_BYTES>>>(qkv, out);
}